// round 16
// baseline (speedup 1.0000x reference)
#include <cuda_runtime.h>
#include <cuda_bf16.h>
#include <cstdint>
#include <cstddef>

// ---------------- problem constants ----------------
#define BB   2
#define TT   2048
#define CC   1024
#define NH   16
#define HD   64
#define MM   (BB * TT)        // 4096
#define KE   2048             // [hi(1024) | lo(1024)] operand layout
#define ROPE_C 0.14391156831212787f

// ---------------- scratch ----------------
__device__ float g_rope[TT * HD];
__device__ float g_bkv[512];
__device__ __nv_bfloat16 g_xe  [(size_t)MM * KE];     // x [hi|lo]
__device__ __nv_bfloat16 g_ae  [(size_t)MM * KE];     // attn out [hi|lo]
__device__ __nv_bfloat16 g_weq [(size_t)CC * KE];     // wq^T [hi|lo]
__device__ __nv_bfloat16 g_wekv[(size_t)512 * KE];    // [wk|wv]^T [hi|lo]
__device__ __nv_bfloat16 g_weo [(size_t)CC * KE];     // wo^T [hi|lo]
__device__ __nv_bfloat16 g_qe  [(size_t)MM * NH * 128];   // Q: [r][h][hi(64)|lo(64)], scaled
__device__ __nv_bfloat16 g_kve [(size_t)MM * 4 * 128];    // K: [r][kvh][hi|lo]
__device__ __nv_bfloat16 g_vt  [(size_t)BB * 4 * 128 * TT]; // V^T: [b][kvh][hi d|lo d][t]

// ---------------- PTX helpers (baseline ISA only) ----------------
__device__ __forceinline__ uint32_t smem_u32(const void* p) {
    uint32_t a;
    asm("{ .reg .u64 t; cvta.to.shared.u64 t, %1; cvt.u32.u64 %0, t; }" : "=r"(a) : "l"(p));
    return a;
}
__device__ __forceinline__ void ldsm_x4(uint32_t* r, uint32_t addr) {
    asm volatile("ldmatrix.sync.aligned.m8n8.x4.shared.b16 {%0,%1,%2,%3}, [%4];"
                 : "=r"(r[0]), "=r"(r[1]), "=r"(r[2]), "=r"(r[3]) : "r"(addr));
}
__device__ __forceinline__ void mma16816(float* d, const uint32_t* a, uint32_t b0, uint32_t b1) {
    asm volatile("mma.sync.aligned.m16n8k16.row.col.f32.bf16.bf16.f32 "
                 "{%0,%1,%2,%3}, {%4,%5,%6,%7}, {%8,%9}, {%0,%1,%2,%3};"
                 : "+f"(d[0]), "+f"(d[1]), "+f"(d[2]), "+f"(d[3])
                 : "r"(a[0]), "r"(a[1]), "r"(a[2]), "r"(a[3]), "r"(b0), "r"(b1));
}
__device__ __forceinline__ void cp16(uint32_t dst, const void* src) {
    asm volatile("cp.async.cg.shared.global [%0], [%1], 16;" :: "r"(dst), "l"(src));
}
#define CP_COMMIT() asm volatile("cp.async.commit_group;" ::: "memory")
#define CP_WAIT1()  asm volatile("cp.async.wait_group 1;" ::: "memory")
#define CP_WAIT0()  asm volatile("cp.async.wait_group 0;" ::: "memory")

__device__ __forceinline__ uint32_t pack_bf2(__nv_bfloat16 x, __nv_bfloat16 y) {
    union { __nv_bfloat162 h; uint32_t u; } c;
    c.h = __nv_bfloat162(x, y);
    return c.u;
}

// ---------------- merged prep kernel ----------------------------------------
__global__ void __launch_bounds__(256)
prep_kernel(const float* __restrict__ x,
            const float* __restrict__ wq, const float* __restrict__ wk,
            const float* __restrict__ wv, const float* __restrict__ wo,
            const float* __restrict__ bk, const float* __restrict__ bv)
{
    // row stride 68 floats = 272 B = multiple of 16 -> float4 ops aligned.
    __shared__ float sm[64][68];
    const int blk = blockIdx.x;
    const int tid = threadIdx.x;

    if (blk < 640) {
        const float* w; __nv_bfloat16* dst; int N, n_off, tt;
        if (blk < 256)      { w = wq; dst = g_weq;  N = 1024; n_off = 0;   tt = blk; }
        else if (blk < 320) { w = wk; dst = g_wekv; N = 256;  n_off = 0;   tt = blk - 256; }
        else if (blk < 384) { w = wv; dst = g_wekv; N = 256;  n_off = 256; tt = blk - 320; }
        else                { w = wo; dst = g_weo;  N = 1024; n_off = 0;   tt = blk - 384; }
        const int tiles_n = N >> 6;
        const int k0 = (tt / tiles_n) << 6;
        const int n0 = (tt % tiles_n) << 6;
        #pragma unroll
        for (int i = 0; i < 4; i++) {
            int e = tid + i * 256;
            int kk = e >> 4, seg = e & 15;
            *(float4*)&sm[kk][seg * 4] = *(const float4*)&w[(size_t)(k0 + kk) * N + n0 + seg * 4];
        }
        __syncthreads();
        const int n = tid >> 2, seg = tid & 3;
        __align__(16) __nv_bfloat16 hi16[16];
        __align__(16) __nv_bfloat16 lo16[16];
        #pragma unroll
        for (int j = 0; j < 16; j++) {
            float v = sm[seg * 16 + j][n];
            __nv_bfloat16 h = __float2bfloat16(v);
            hi16[j] = h;
            lo16[j] = __float2bfloat16(v - __bfloat162float(h));
        }
        __nv_bfloat16* base = dst + (size_t)(n_off + n0 + n) * KE + k0 + seg * 16;
        *(uint4*)(base)        = *(uint4*)&hi16[0];
        *(uint4*)(base + 8)    = *(uint4*)&hi16[8];
        *(uint4*)(base + 1024) = *(uint4*)&lo16[0];
        *(uint4*)(base + 1032) = *(uint4*)&lo16[8];
    } else if (blk < 2688) {
        const int idx = (blk - 640) * 2048 + tid * 8;
        const int r = idx >> 10, k = idx & 1023;
        float4 v0 = *(const float4*)&x[idx];
        float4 v1 = *(const float4*)&x[idx + 4];
        float f[8] = { v0.x, v0.y, v0.z, v0.w, v1.x, v1.y, v1.z, v1.w };
        __align__(16) __nv_bfloat16 hi[8];
        __align__(16) __nv_bfloat16 lo[8];
        #pragma unroll
        for (int j = 0; j < 8; j++) {
            hi[j] = __float2bfloat16(f[j]);
            lo[j] = __float2bfloat16(f[j] - __bfloat162float(hi[j]));
        }
        __nv_bfloat16* base = g_xe + (size_t)r * KE + k;
        *(uint4*)(base)        = *(uint4*)&hi[0];
        *(uint4*)(base + 1024) = *(uint4*)&lo[0];
    } else if (blk < 2944) {
        const int id = (blk - 2688) * 256 + tid;
        const int t = id >> 5, p = id & 31;
        float inv = expf(-(float)(2 * p) * ROPE_C);
        float sn, cs;
        sincosf((float)t * inv, &sn, &cs);
        g_rope[t * HD + 2 * p]     = cs;
        g_rope[t * HD + 2 * p + 1] = sn;
    } else {
        const int i = (blk - 2944) * 256 + tid;
        g_bkv[i] = (i < 256) ? bk[i] : bv[i - 256];
    }
}

// ---------------- HMMA GEMM: 128x128 tile, 8 warps, BK=64 -------------------
#define GSM_TOTAL (3 * 32768)

__device__ __forceinline__ void pass_offsets(int it, int& ka, int& kb) {
    const int pass = it >> 4, kc = it & 15;
    ka = ((pass == 2) ? 1024 : 0) + kc * 64;
    kb = ((pass == 1) ? 1024 : 0) + kc * 64;
}

__device__ __forceinline__ void stage_async(uint32_t dstA, uint32_t dstB,
                                            const __nv_bfloat16* Ap, const __nv_bfloat16* Wp,
                                            int ka, int kb, int tid)
{
    #pragma unroll
    for (int i = 0; i < 4; i++) {
        int e   = tid + i * 256;
        int row = e >> 3, ch = e & 7;
        uint32_t sw = row * 128 + ((ch ^ (row & 7)) << 4);
        cp16(dstA + sw, Ap + (size_t)row * KE + ka + ch * 8);
        cp16(dstB + sw, Wp + (size_t)row * KE + kb + ch * 8);
    }
}

__global__ void __launch_bounds__(256, 2)
mma_gemm(const __nv_bfloat16* __restrict__ A,
         const __nv_bfloat16* __restrict__ W0, const float* __restrict__ b0,
         const __nv_bfloat16* __restrict__ W1, const float* __restrict__ b1,
         float* __restrict__ C, int ldc, int split, int mode0_val)
{
    extern __shared__ char smem[];
    const uint32_t sb = smem_u32(smem);

    const int tid  = threadIdx.x;
    const int wid  = tid >> 5;
    const int lane = tid & 31;
    const int warpRow = wid & 1;
    const int warpCol = wid >> 1;
    const int row0 = blockIdx.y * 128;
    const int gcol0 = blockIdx.x * 128;

    const __nv_bfloat16* W; const float* bias; int wc0, mode;
    if (gcol0 < split) { W = W0; bias = b0; wc0 = gcol0;         mode = mode0_val; }
    else               { W = W1; bias = b1; wc0 = gcol0 - split; mode = 1; }

    const __nv_bfloat16* Ap = A + (size_t)row0 * KE;
    const __nv_bfloat16* Wp = W + (size_t)wc0 * KE;

    const int rx   = lane & 7;
    const int rowA = warpRow * 64 + (lane & 7) + ((lane >> 3) & 1) * 8;
    const int hiA  = (lane >> 4) & 1;
    const int rowB = warpCol * 32 + (lane & 7) + ((lane >> 4) & 1) * 8;
    const int hiB  = (lane >> 3) & 1;

    float acc[4][4][4];
    #pragma unroll
    for (int mi = 0; mi < 4; mi++)
        #pragma unroll
        for (int nb = 0; nb < 4; nb++)
            #pragma unroll
            for (int q = 0; q < 4; q++) acc[mi][nb][q] = 0.f;

    const int NIT = 48;
    {
        int ka, kb2; pass_offsets(0, ka, kb2);
        stage_async(sb, sb + 16384, Ap, Wp, ka, kb2, tid);
        CP_COMMIT();
    }

    for (int it = 0; it < NIT; it++) {
        if (it + 1 < NIT) {
            const uint32_t nb_ = sb + ((it + 1) % 3) * 32768;
            int ka, kb2; pass_offsets(it + 1, ka, kb2);
            stage_async(nb_, nb_ + 16384, Ap, Wp, ka, kb2, tid);
            CP_COMMIT();
            CP_WAIT1();
        } else {
            CP_WAIT0();
        }
        __syncthreads();

        const uint32_t bufc = sb + (it % 3) * 32768;
        const uint32_t aBase = bufc + rowA * 128;
        const uint32_t bBase = bufc + 16384 + rowB * 128;
        #pragma unroll
        for (int kk = 0; kk < 4; kk++) {
            uint32_t a[4][4], b[2][4];
            #pragma unroll
            for (int mi = 0; mi < 4; mi++)
                ldsm_x4(a[mi], aBase + mi * 2048 + ((((kk * 2 + hiA) ^ rx)) << 4));
            #pragma unroll
            for (int nj = 0; nj < 2; nj++)
                ldsm_x4(b[nj], bBase + nj * 2048 + ((((kk * 2 + hiB) ^ rx)) << 4));
            #pragma unroll
            for (int mi = 0; mi < 4; mi++) {
                mma16816(acc[mi][0], a[mi], b[0][0], b[0][1]);
                mma16816(acc[mi][1], a[mi], b[0][2], b[0][3]);
                mma16816(acc[mi][2], a[mi], b[1][0], b[1][1]);
                mma16816(acc[mi][3], a[mi], b[1][2], b[1][3]);
            }
        }
    }

    const int g  = lane >> 2;
    const int tg = lane & 3;
    #pragma unroll
    for (int mi = 0; mi < 4; mi++) {
        #pragma unroll
        for (int nb = 0; nb < 4; nb++) {
            const int col = wc0 + warpCol * 32 + nb * 8 + tg * 2;
            const float bx = bias[col], by = bias[col + 1];
            const bool rp = (mode == 0) || (mode == 1 && col < 256);
            #pragma unroll
            for (int half = 0; half < 2; half++) {
                const int r = row0 + warpRow * 64 + mi * 16 + g + half * 8;
                float x = acc[mi][nb][half * 2]     + bx;
                float y = acc[mi][nb][half * 2 + 1] + by;
                if (rp) {
                    const int t = r & (TT - 1);
                    float2 cn = *(const float2*)&g_rope[t * HD + (col & (HD - 1))];
                    float e = x, o = y;
                    x = e * cn.x - o * cn.y;
                    y = e * cn.y + o * cn.x;
                }
                if (mode == 2) {
                    *(float2*)(C + (size_t)r * ldc + col) = make_float2(x, y);
                } else if (mode == 0) {
                    x *= 0.125f; y *= 0.125f;
                    __nv_bfloat16 hx = __float2bfloat16(x), hy = __float2bfloat16(y);
                    __nv_bfloat16 lx = __float2bfloat16(x - __bfloat162float(hx));
                    __nv_bfloat16 ly = __float2bfloat16(y - __bfloat162float(hy));
                    const int h = col >> 6, d = col & 63;
                    uint32_t* p = (uint32_t*)&g_qe[((size_t)r * NH + h) * 128 + d];
                    p[0]  = pack_bf2(hx, hy);
                    p[32] = pack_bf2(lx, ly);
                } else {
                    __nv_bfloat16 hx = __float2bfloat16(x), hy = __float2bfloat16(y);
                    __nv_bfloat16 lx = __float2bfloat16(x - __bfloat162float(hx));
                    __nv_bfloat16 ly = __float2bfloat16(y - __bfloat162float(hy));
                    if (col < 256) {
                        const int h = col >> 6, d = col & 63;
                        uint32_t* p = (uint32_t*)&g_kve[((size_t)r * 4 + h) * 128 + d];
                        p[0]  = pack_bf2(hx, hy);
                        p[32] = pack_bf2(lx, ly);
                    } else {
                        const int cv = col - 256, h = cv >> 6, d = cv & 63;
                        const int bb = r >> 11, t = r & (TT - 1);
                        __nv_bfloat16* p = &g_vt[(((size_t)(bb * 4 + h) * 128) + d) * TT + t];
                        p[0]        = hx;
                        p[TT]       = hy;
                        p[64 * TT]  = lx;
                        p[65 * TT]  = ly;
                    }
                }
            }
        }
    }
}

// ---------------- tensor-core flash attention -------------------------------
// Fragment-reuse restructure: per kc load aH/aL once, per nt2 load bH/bL once,
// issue all 3 split-passes' MMAs together. Same for PV with vH/vL.
#define AT_QS   0
#define AT_K0   32768
#define AT_V0   65536
#define AT_TOTAL 98304

__device__ __forceinline__ void load_kv_chunk(uint32_t sb, int buf, int b, int kvh,
                                              int t0, int tid)
{
    const __nv_bfloat16* kg = &g_kve[((size_t)(b * TT + t0) * 4 + kvh) * 128];
    const uint32_t kdst = sb + AT_K0 + buf * 16384;
    #pragma unroll
    for (int i = 0; i < 4; i++) {
        int e = tid + i * 256, c = e >> 4, ch = e & 15;
        cp16(kdst + c * 256 + (((ch & 8) | ((ch ^ c) & 7)) << 4), kg + (size_t)c * 512 + ch * 8);
    }
    const __nv_bfloat16* vg = &g_vt[(size_t)(b * 4 + kvh) * 128 * TT + t0];
    const uint32_t vdst = sb + AT_V0 + buf * 16384;
    #pragma unroll
    for (int i = 0; i < 4; i++) {
        int e = tid + i * 256, d = e >> 3, ch = e & 7;
        cp16(vdst + d * 128 + (((ch ^ d) & 7) << 4), vg + (size_t)d * TT + ch * 8);
    }
}

__global__ void __launch_bounds__(256, 2)
attn_kernel()
{
    extern __shared__ char smem[];
    const uint32_t sb = smem_u32(smem);

    const int b  = blockIdx.z;
    const int h  = blockIdx.y;
    const int qt = gridDim.x - 1 - blockIdx.x;   // heavy tiles first
    const int kvh = h >> 2;
    const int tid  = threadIdx.x;
    const int w    = tid >> 5;
    const int lane = tid & 31;
    const int g    = lane >> 2;
    const int tg   = lane & 3;

    {
        const __nv_bfloat16* qg = &g_qe[((size_t)(b * TT + qt * 128) * NH + h) * 128];
        #pragma unroll
        for (int i = 0; i < 8; i++) {
            int e = tid + i * 256, r = e >> 4, ch = e & 15;
            cp16(sb + AT_QS + r * 256 + (((ch & 8) | ((ch ^ r) & 7)) << 4),
                 qg + (size_t)r * (NH * 128) + ch * 8);
        }
    }
    CP_COMMIT();
    load_kv_chunk(sb, 0, b, kvh, 0, tid);
    CP_COMMIT();

    const int qrow = w * 16 + (lane & 7) + ((lane >> 3) & 1) * 8;
    const int hiA  = (lane >> 4) & 1;
    const int brow = (lane & 7) + ((lane >> 4) & 1) * 8;
    const int hiB  = (lane >> 3) & 1;
    const uint32_t aBase = sb + AT_QS + qrow * 256;

    float m0 = -3.0e38f, m1 = -3.0e38f, l0 = 0.f, l1 = 0.f;
    float ov[8][4];
    #pragma unroll
    for (int nt = 0; nt < 8; nt++)
        #pragma unroll
        for (int q = 0; q < 4; q++) ov[nt][q] = 0.f;

    const int jend = 2 * qt + 1;
    for (int jt = 0; jt <= jend; jt++) {
        if (jt < jend) { load_kv_chunk(sb, (jt + 1) & 1, b, kvh, (jt + 1) * 64, tid); CP_COMMIT(); CP_WAIT1(); }
        else CP_WAIT0();
        __syncthreads();

        const int buf = jt & 1;
        const uint32_t kBase = sb + AT_K0 + buf * 16384;
        const uint32_t vBase = sb + AT_V0 + buf * 16384;

        // ---- S = Qe @ Ke^T with fragment reuse ----
        float sv[8][4];
        #pragma unroll
        for (int nt = 0; nt < 8; nt++)
            #pragma unroll
            for (int q = 0; q < 4; q++) sv[nt][q] = 0.f;

        #pragma unroll
        for (int kc = 0; kc < 4; kc++) {
            uint32_t aH[4], aL[4];
            const int chAH = 2 * kc + hiA;          // hi plane (chunks 0..7)
            const int chAL = 8 + 2 * kc + hiA;      // lo plane (chunks 8..15)
            ldsm_x4(aH, aBase + (((chAH & 8) | ((chAH ^ qrow) & 7)) << 4));
            ldsm_x4(aL, aBase + (((chAL & 8) | ((chAL ^ qrow) & 7)) << 4));
            #pragma unroll
            for (int nt2 = 0; nt2 < 4; nt2++) {
                const int c = nt2 * 16 + brow;
                uint32_t bH[4], bL[4];
                const int chBH = 2 * kc + hiB;
                const int chBL = 8 + 2 * kc + hiB;
                ldsm_x4(bH, kBase + c * 256 + (((chBH & 8) | ((chBH ^ c) & 7)) << 4));
                ldsm_x4(bL, kBase + c * 256 + (((chBL & 8) | ((chBL ^ c) & 7)) << 4));
                mma16816(sv[nt2 * 2],     aH, bH[0], bH[1]);
                mma16816(sv[nt2 * 2 + 1], aH, bH[2], bH[3]);
                mma16816(sv[nt2 * 2],     aH, bL[0], bL[1]);
                mma16816(sv[nt2 * 2 + 1], aH, bL[2], bL[3]);
                mma16816(sv[nt2 * 2],     aL, bH[0], bH[1]);
                mma16816(sv[nt2 * 2 + 1], aL, bH[2], bH[3]);
            }
        }

        // ---- causal mask ----
        const int kc0 = jt * 64;
        if (kc0 + 63 > qt * 128 + w * 16) {
            #pragma unroll
            for (int nt = 0; nt < 8; nt++)
                #pragma unroll
                for (int q = 0; q < 4; q++) {
                    const int row = qt * 128 + w * 16 + g + 8 * (q >> 1);
                    const int col = kc0 + nt * 8 + tg * 2 + (q & 1);
                    if (col > row) sv[nt][q] = -1.0e30f;
                }
        }

        // ---- online softmax ----
        float mx0 = -3.0e38f, mx1 = -3.0e38f;
        #pragma unroll
        for (int nt = 0; nt < 8; nt++) {
            mx0 = fmaxf(mx0, fmaxf(sv[nt][0], sv[nt][1]));
            mx1 = fmaxf(mx1, fmaxf(sv[nt][2], sv[nt][3]));
        }
        mx0 = fmaxf(mx0, __shfl_xor_sync(0xffffffffu, mx0, 1));
        mx0 = fmaxf(mx0, __shfl_xor_sync(0xffffffffu, mx0, 2));
        mx1 = fmaxf(mx1, __shfl_xor_sync(0xffffffffu, mx1, 1));
        mx1 = fmaxf(mx1, __shfl_xor_sync(0xffffffffu, mx1, 2));
        const float mn0 = fmaxf(m0, mx0), mn1 = fmaxf(m1, mx1);
        const float al0 = __expf(m0 - mn0), al1 = __expf(m1 - mn1);
        float rs0 = 0.f, rs1 = 0.f;
        #pragma unroll
        for (int nt = 0; nt < 8; nt++) {
            sv[nt][0] = __expf(sv[nt][0] - mn0); rs0 += sv[nt][0];
            sv[nt][1] = __expf(sv[nt][1] - mn0); rs0 += sv[nt][1];
            sv[nt][2] = __expf(sv[nt][2] - mn1); rs1 += sv[nt][2];
            sv[nt][3] = __expf(sv[nt][3] - mn1); rs1 += sv[nt][3];
        }
        rs0 += __shfl_xor_sync(0xffffffffu, rs0, 1);
        rs0 += __shfl_xor_sync(0xffffffffu, rs0, 2);
        rs1 += __shfl_xor_sync(0xffffffffu, rs1, 1);
        rs1 += __shfl_xor_sync(0xffffffffu, rs1, 2);
        l0 = l0 * al0 + rs0; l1 = l1 * al1 + rs1;
        m0 = mn0; m1 = mn1;
        #pragma unroll
        for (int nt = 0; nt < 8; nt++) {
            ov[nt][0] *= al0; ov[nt][1] *= al0;
            ov[nt][2] *= al1; ov[nt][3] *= al1;
        }

        // ---- O += P @ V with fragment reuse ----
        #pragma unroll
        for (int cc = 0; cc < 4; cc++) {
            uint32_t aph[4], apl[4];
            aph[0] = pack_bf2(__float2bfloat16(sv[2*cc][0]),   __float2bfloat16(sv[2*cc][1]));
            aph[1] = pack_bf2(__float2bfloat16(sv[2*cc][2]),   __float2bfloat16(sv[2*cc][3]));
            aph[2] = pack_bf2(__float2bfloat16(sv[2*cc+1][0]), __float2bfloat16(sv[2*cc+1][1]));
            aph[3] = pack_bf2(__float2bfloat16(sv[2*cc+1][2]), __float2bfloat16(sv[2*cc+1][3]));
            {
                float p0 = sv[2*cc][0],   p1 = sv[2*cc][1];
                float p2 = sv[2*cc][2],   p3 = sv[2*cc][3];
                float p4 = sv[2*cc+1][0], p5 = sv[2*cc+1][1];
                float p6 = sv[2*cc+1][2], p7 = sv[2*cc+1][3];
                apl[0] = pack_bf2(__float2bfloat16(p0 - __bfloat162float(__float2bfloat16(p0))),
                                  __float2bfloat16(p1 - __bfloat162float(__float2bfloat16(p1))));
                apl[1] = pack_bf2(__float2bfloat16(p2 - __bfloat162float(__float2bfloat16(p2))),
                                  __float2bfloat16(p3 - __bfloat162float(__float2bfloat16(p3))));
                apl[2] = pack_bf2(__float2bfloat16(p4 - __bfloat162float(__float2bfloat16(p4))),
                                  __float2bfloat16(p5 - __bfloat162float(__float2bfloat16(p5))));
                apl[3] = pack_bf2(__float2bfloat16(p6 - __bfloat162float(__float2bfloat16(p6))),
                                  __float2bfloat16(p7 - __bfloat162float(__float2bfloat16(p7))));
            }
            #pragma unroll
            for (int nt2 = 0; nt2 < 4; nt2++) {
                const int dH = nt2 * 16 + brow;           // V hi plane rows
                const int dL = 64 + nt2 * 16 + brow;      // V lo plane rows
                const int chV = 2 * cc + hiB;
                uint32_t vH[4], vL[4];
                ldsm_x4(vH, vBase + dH * 128 + (((chV ^ dH) & 7) << 4));
                ldsm_x4(vL, vBase + dL * 128 + (((chV ^ dL) & 7) << 4));
                mma16816(ov[nt2 * 2],     aph, vH[0], vH[1]);
                mma16816(ov[nt2 * 2 + 1], aph, vH[2], vH[3]);
                mma16816(ov[nt2 * 2],     aph, vL[0], vL[1]);
                mma16816(ov[nt2 * 2 + 1], aph, vL[2], vL[3]);
                mma16816(ov[nt2 * 2],     apl, vH[0], vH[1]);
                mma16816(ov[nt2 * 2 + 1], apl, vH[2], vH[3]);
            }
        }
        __syncthreads();
    }

    const float i0 = 1.f / l0, i1 = 1.f / l1;
    const size_t r0g = (size_t)(b * TT + qt * 128 + w * 16 + g);
    #pragma unroll
    for (int nt = 0; nt < 8; nt++) {
        const int dg = h * 64 + nt * 8 + tg * 2;
        #pragma unroll
        for (int half = 0; half < 2; half++) {
            const float x = ov[nt][half * 2]     * (half ? i1 : i0);
            const float y = ov[nt][half * 2 + 1] * (half ? i1 : i0);
            __nv_bfloat16 hx = __float2bfloat16(x), hy = __float2bfloat16(y);
            __nv_bfloat16 lx = __float2bfloat16(x - __bfloat162float(hx));
            __nv_bfloat16 ly = __float2bfloat16(y - __bfloat162float(hy));
            uint32_t* p = (uint32_t*)&g_ae[(r0g + half * 8) * KE + dg];
            p[0]   = pack_bf2(hx, hy);
            p[512] = pack_bf2(lx, ly);
        }
    }
}

// ---------------- launch ----------------
extern "C" void kernel_launch(void* const* d_in, const int* in_sizes, int n_in,
                              void* d_out, int out_size)
{
    (void)in_sizes; (void)n_in; (void)out_size;
    const float* x  = (const float*)d_in[0];
    const float* wq = (const float*)d_in[1];
    const float* bq = (const float*)d_in[2];
    const float* wk = (const float*)d_in[3];
    const float* bk = (const float*)d_in[4];
    const float* wv = (const float*)d_in[5];
    const float* bv = (const float*)d_in[6];
    const float* wo = (const float*)d_in[7];
    const float* bo = (const float*)d_in[8];
    float* out = (float*)d_out;

    float* bkv;
    __nv_bfloat16 *xe, *ae, *weq, *wekv, *weo;
    cudaGetSymbolAddress((void**)&bkv,  g_bkv);
    cudaGetSymbolAddress((void**)&xe,   g_xe);
    cudaGetSymbolAddress((void**)&ae,   g_ae);
    cudaGetSymbolAddress((void**)&weq,  g_weq);
    cudaGetSymbolAddress((void**)&wekv, g_wekv);
    cudaGetSymbolAddress((void**)&weo,  g_weo);

    cudaFuncSetAttribute(mma_gemm,    cudaFuncAttributeMaxDynamicSharedMemorySize, GSM_TOTAL);
    cudaFuncSetAttribute(attn_kernel, cudaFuncAttributeMaxDynamicSharedMemorySize, AT_TOTAL);

    // merged prep: weight transposes + x split + rope + bias pack
    prep_kernel<<<2946, 256>>>(x, wq, wk, wv, wo, bk, bv);

    // fused Q + KV projection: cols [0,1024) -> Q (mode 0), [1024,1536) -> KV (mode 1)
    mma_gemm<<<dim3(12, 32), 256, GSM_TOTAL>>>(xe, weq, bq, wekv, bkv, nullptr, 0, 1024, 0);

    attn_kernel<<<dim3(TT / 128, NH, BB), 256, AT_TOTAL>>>();

    // O proj -> fp32 out (mode 2)
    mma_gemm<<<dim3(8, 32), 256, GSM_TOTAL>>>(ae, weo, bo, weo, bo, out, CC, 1024, 2);
}